// round 5
// baseline (speedup 1.0000x reference)
#include <cuda_runtime.h>
#include <stdint.h>

// FP32 "pulse bits" (B,32 floats of 0.0/1.0, MSB-first) -> FP64 "pulse bits" (B,64).
// Semantics: fp32 fields s|e|m -> fp64: exp11 = 0 (e==0), 2047 (e==255), else e+896;
// mant52 = m<<29 normally, quiet-bit only (1<<51) for NaN, 0 for Inf.
//
// One WARP per row:
//  - lane l loads input float l          -> 1 coalesced 128B LDG.32 (1 wavefront)
//  - __ballot_sync packs 32 bits         -> 1 VOTE instr (+brev for MSB-first)
//  - all lanes redundantly compute the fp64 pattern (hi,lo) in ~10 ALU ops
//  - lane l stores output words 2l,2l+1  -> 1 coalesced 256B STG.64
// Pure streaming, 768 MB total -> DRAM-bound; target ~120-140 us on GB300.

#define ROWS_PER_WARP 16
#define THREADS 256

__global__ void __launch_bounds__(THREADS)
fp32bits_to_fp64bits_kernel(const unsigned* __restrict__ in,
                            uint2* __restrict__ out,
                            int nrows)
{
    const int lane   = threadIdx.x & 31;
    const int warpId = (blockIdx.x * blockDim.x + threadIdx.x) >> 5;
    const int row0   = warpId * ROWS_PER_WARP;

    const unsigned ONE = 0x3F800000u;        // bits of 1.0f

    // Lane -> output mapping: lanes 0-15 emit from hi word, 16-31 from lo word.
    const int  ll    = lane & 15;            // bit-pair index within source word
    const int  sh_x  = 31 - 2 * ll;          // bit for output word 2*lane
    const int  sh_y  = 30 - 2 * ll;          // bit for output word 2*lane+1
    const bool useHi = lane < 16;

    #pragma unroll 4
    for (int r = 0; r < ROWS_PER_WARP; r++) {
        const int row = row0 + r;
        if (row >= nrows) return;

        // ---- load + pack ----
        unsigned v   = __ldcs(in + (size_t)row * 32 + lane);
        unsigned bal = __ballot_sync(0xFFFFFFFFu, v != 0u);
        unsigned u   = __brev(bal);          // bit31 = input index 0 (sign)

        // ---- fp32 fields -> fp64 bit pattern ----
        unsigned s = u >> 31;
        unsigned e = (u >> 23) & 0xFFu;
        unsigned m = u & 0x7FFFFFu;

        unsigned exp11  = (e == 0u) ? 0u : (e + 896u);
        unsigned mant23 = m;                           // top 23 of mant52
        if (e == 255u) {
            exp11  = 2047u;
            mant23 = m ? (1u << 22) : 0u;              // NaN -> quiet bit; Inf -> 0
        }

        unsigned hi = (s << 31) | (exp11 << 20) | (mant23 >> 3);
        unsigned lo = mant23 << 29;                    // only bits 31..29 may be set

        // ---- emit ----
        unsigned src = useHi ? hi : lo;
        uint2 o;
        o.x = ((src >> sh_x) & 1u) ? ONE : 0u;
        o.y = ((src >> sh_y) & 1u) ? ONE : 0u;
        __stcs(out + (size_t)row * 32 + lane, o);
    }
}

extern "C" void kernel_launch(void* const* d_in, const int* in_sizes, int n_in,
                              void* d_out, int out_size)
{
    const unsigned* in  = (const unsigned*)d_in[0];
    uint2*          out = (uint2*)d_out;
    const int nrows = in_sizes[0] / 32;

    const int warps  = (nrows + ROWS_PER_WARP - 1) / ROWS_PER_WARP;
    const int blocks = (warps + (THREADS / 32) - 1) / (THREADS / 32);
    fp32bits_to_fp64bits_kernel<<<blocks, THREADS>>>(in, out, nrows);
}

// round 6
// speedup vs baseline: 1.4980x; 1.4980x over previous
#include <cuda_runtime.h>
#include <stdint.h>

// FP32 "pulse bits" (B,32 floats of 0.0/1.0, MSB-first) -> FP64 "pulse bits" (B,64).
// fp64: exp11 = 0 (e==0), 2047 (e==255), else e+896; mant52 = m<<29, NaN -> 1<<51, Inf -> 0.
//
// One WARP per R rows, software-pipelined:
//   Phase 1: issue R back-to-back coalesced LDG.32 (lane l <- float l of each row)
//            -> R*128B in flight per warp (MLP_p1 = R) to cover ~577cyc DRAM latency.
//   Phase 2: per row: 1 VOTE (ballot pack) + ~14 ALU decode + 1 coalesced STG.64.
// R5 finding: unroll-4 interleaved version was concurrency-bound at 53% DRAM (180us).

#define R 8
#define THREADS 256

__global__ void __launch_bounds__(THREADS)
fp32bits_to_fp64bits_kernel(const unsigned* __restrict__ in,
                            uint2* __restrict__ out,
                            int nrows)
{
    const int lane   = threadIdx.x & 31;
    const int warpId = (int)((blockIdx.x * blockDim.x + threadIdx.x) >> 5);
    const size_t row0 = (size_t)warpId * R;
    if (row0 >= (size_t)nrows) return;

    const unsigned ONE  = 0x3F800000u;     // bits of 1.0f
    const int      sh_y = 30 - 2 * (lane & 15);   // low bit of this lane's 2-bit field
    const bool     useHi = lane < 16;

    const unsigned* p = in + row0 * 32 + lane;
    uint2* q = out + row0 * 32 + lane;

    if (row0 + R <= (size_t)nrows) {
        // ---- Phase 1: batch all loads (maximize bytes in flight) ----
        unsigned v[R];
        #pragma unroll
        for (int r = 0; r < R; r++) v[r] = __ldcs(p + r * 32);

        // ---- Phase 2: pack, decode, store ----
        #pragma unroll
        for (int r = 0; r < R; r++) {
            unsigned u = __brev(__ballot_sync(0xFFFFFFFFu, v[r] != 0u));

            unsigned e = (u >> 23) & 0xFFu;
            unsigned m = u & 0x7FFFFFu;

            unsigned exp11  = (e == 0u) ? 0u : (e + 896u);
            unsigned mant23 = m;
            if (e == 255u) {                       // Inf / NaN
                exp11  = 2047u;
                mant23 = m ? (1u << 22) : 0u;      // NaN -> quiet bit only
            }

            unsigned hi = (u & 0x80000000u) | (exp11 << 20) | (mant23 >> 3);
            unsigned lo = mant23 << 29;            // only bits 31..29 may be set

            unsigned src = useHi ? hi : lo;
            unsigned two = (src >> sh_y) & 3u;     // this lane's 2 output bits
            uint2 o;
            o.x = (two & 2u) ? ONE : 0u;
            o.y = (two & 1u) ? ONE : 0u;
            __stcs(q + r * 32, o);
        }
    } else {
        // Tail (not hit for B = 2^21, kept for safety)
        for (int r = 0; r < R && row0 + r < (size_t)nrows; r++) {
            unsigned v = __ldcs(p + r * 32);
            unsigned u = __brev(__ballot_sync(0xFFFFFFFFu, v != 0u));
            unsigned e = (u >> 23) & 0xFFu;
            unsigned m = u & 0x7FFFFFu;
            unsigned exp11  = (e == 0u) ? 0u : (e + 896u);
            unsigned mant23 = m;
            if (e == 255u) { exp11 = 2047u; mant23 = m ? (1u << 22) : 0u; }
            unsigned hi = (u & 0x80000000u) | (exp11 << 20) | (mant23 >> 3);
            unsigned lo = mant23 << 29;
            unsigned src = useHi ? hi : lo;
            unsigned two = (src >> sh_y) & 3u;
            uint2 o;
            o.x = (two & 2u) ? ONE : 0u;
            o.y = (two & 1u) ? ONE : 0u;
            __stcs(q + r * 32, o);
        }
    }
}

extern "C" void kernel_launch(void* const* d_in, const int* in_sizes, int n_in,
                              void* d_out, int out_size)
{
    const unsigned* in  = (const unsigned*)d_in[0];
    uint2*          out = (uint2*)d_out;
    const int nrows = in_sizes[0] / 32;

    const int warps  = (nrows + R - 1) / R;
    const int blocks = (warps + (THREADS / 32) - 1) / (THREADS / 32);
    fp32bits_to_fp64bits_kernel<<<blocks, THREADS>>>(in, out, nrows);
}